// round 2
// baseline (speedup 1.0000x reference)
#include <cuda_runtime.h>
#include <cuda_fp16.h>

#define N_USERS 100000
#define N_ITEMS 200000
#define N_NODES (N_USERS + N_ITEMS)
#define NNZ     9600000
#define DIM     64
#define TOTAL   ((size_t)N_NODES * DIM)
#define TOTAL4  (TOTAL / 4)

// Scratch (alloc-free rule: __device__ globals).
// g_sum : fp32 scatter/accumulate target for the current layer's SpMM.
// g_half: fp16 copy of the current layer's embedding — the gather source.
//         38.4MB + 76.8MB = 115MB -> fits the 126MB L2 together.
__device__ __align__(16) float  g_sum[TOTAL];
__device__ __align__(16) __half g_half[TOTAL];

// ---------------------------------------------------------------------------
// init: acc(out) = concat(user,item); g_half = fp16(same); g_sum = 0.
// Re-done every call so graph replay is deterministic.
// ---------------------------------------------------------------------------
__global__ __launch_bounds__(256) void init_kernel(
    const float* __restrict__ user_emb,
    const float* __restrict__ item_emb,
    float* __restrict__ out)
{
    size_t i = (size_t)blockIdx.x * blockDim.x + threadIdx.x;
    if (i >= TOTAL4) return;
    const size_t ub = (size_t)N_USERS * DIM / 4;
    float4 v = (i < ub) ? ((const float4*)user_emb)[i]
                        : ((const float4*)item_emb)[i - ub];
    ((float4*)out)[i] = v;
    __half2 h01 = __floats2half2_rn(v.x, v.y);
    __half2 h23 = __floats2half2_rn(v.z, v.w);
    ((__half2*)g_half)[i * 2]     = h01;
    ((__half2*)g_half)[i * 2 + 1] = h23;
    ((float4*)g_sum)[i] = make_float4(0.f, 0.f, 0.f, 0.f);
}

// ---------------------------------------------------------------------------
// SpMM scatter: 8 threads per edge. Each thread gathers 8 halfs (16B) from
// the fp16 src table (L2-resident), scales in fp32, and fires two
// red.global.add.v4.f32 (fire-and-forget) into the fp32 sum buffer.
// ---------------------------------------------------------------------------
__global__ __launch_bounds__(256) void spmm_kernel(
    const int*   __restrict__ rows,
    const int*   __restrict__ cols,
    const float* __restrict__ vals,
    float*       __restrict__ dst)
{
    long long t = (long long)blockIdx.x * blockDim.x + threadIdx.x;
    long long e = t >> 3;
    if (e >= NNZ) return;
    int sub = (int)(t & 7);                 // 8 subs x 8 floats = 64 dims

    int   r = __ldg(rows + e);
    int   c = __ldg(cols + e);
    float v = __ldg(vals + e);

    // 8 halfs = 16 bytes
    const uint4* sp = (const uint4*)((const char*)g_half +
                                     (size_t)c * (DIM * 2) + (size_t)sub * 16);
    uint4 raw = __ldg(sp);

    float2 f0 = __half22float2(*(const __half2*)&raw.x);
    float2 f1 = __half22float2(*(const __half2*)&raw.y);
    float2 f2 = __half22float2(*(const __half2*)&raw.z);
    float2 f3 = __half22float2(*(const __half2*)&raw.w);

    float* p = dst + (size_t)r * DIM + (size_t)sub * 8;
    asm volatile("red.global.add.v4.f32 [%0], {%1,%2,%3,%4};"
                 :: "l"(p),
                    "f"(f0.x * v), "f"(f0.y * v), "f"(f1.x * v), "f"(f1.y * v)
                 : "memory");
    asm volatile("red.global.add.v4.f32 [%0], {%1,%2,%3,%4};"
                 :: "l"(p + 4),
                    "f"(f2.x * v), "f"(f2.y * v), "f"(f3.x * v), "f"(f3.y * v)
                 : "memory");
}

// ---------------------------------------------------------------------------
// acc += sum; g_half = fp16(sum) for the next layer's gather; g_sum = 0.
// ---------------------------------------------------------------------------
__global__ __launch_bounds__(256) void accum_kernel(
    float* __restrict__ acc)
{
    size_t i = (size_t)blockIdx.x * blockDim.x + threadIdx.x;
    if (i >= TOTAL4) return;
    float4 s = ((const float4*)g_sum)[i];
    float4 a = ((float4*)acc)[i];
    a.x += s.x; a.y += s.y; a.z += s.z; a.w += s.w;
    ((float4*)acc)[i] = a;
    ((__half2*)g_half)[i * 2]     = __floats2half2_rn(s.x, s.y);
    ((__half2*)g_half)[i * 2 + 1] = __floats2half2_rn(s.z, s.w);
    ((float4*)g_sum)[i] = make_float4(0.f, 0.f, 0.f, 0.f);
}

// Final layer: out = (acc + sum) * 0.25. No fp16 write, no re-zero needed.
__global__ __launch_bounds__(256) void accum_final_kernel(
    float* __restrict__ acc)
{
    size_t i = (size_t)blockIdx.x * blockDim.x + threadIdx.x;
    if (i >= TOTAL4) return;
    float4 s = ((const float4*)g_sum)[i];
    float4 a = ((float4*)acc)[i];
    a.x = (a.x + s.x) * 0.25f;
    a.y = (a.y + s.y) * 0.25f;
    a.z = (a.z + s.z) * 0.25f;
    a.w = (a.w + s.w) * 0.25f;
    ((float4*)acc)[i] = a;
}

extern "C" void kernel_launch(void* const* d_in, const int* in_sizes, int n_in,
                              void* d_out, int out_size)
{
    const int*   rows     = (const int*)  d_in[0];
    const int*   cols     = (const int*)  d_in[1];
    const float* vals     = (const float*)d_in[2];
    const float* user_emb = (const float*)d_in[3];
    const float* item_emb = (const float*)d_in[4];
    float*       out      = (float*)d_out;

    float* sum;
    cudaGetSymbolAddress((void**)&sum, g_sum);

    const int thr = 256;
    const long long spmm_threads = (long long)NNZ * 8;
    const int spmm_blocks = (int)((spmm_threads + thr - 1) / thr);
    const int vec_blocks  = (int)((TOTAL4 + thr - 1) / thr);

    // acc = input ; g_half = fp16(input) ; g_sum = 0
    init_kernel<<<vec_blocks, thr>>>(user_emb, item_emb, out);

    // Layer 0
    spmm_kernel<<<spmm_blocks, thr>>>(rows, cols, vals, sum);
    accum_kernel<<<vec_blocks, thr>>>(out);

    // Layer 1
    spmm_kernel<<<spmm_blocks, thr>>>(rows, cols, vals, sum);
    accum_kernel<<<vec_blocks, thr>>>(out);

    // Layer 2 (final): out = (acc + sum) / 4
    spmm_kernel<<<spmm_blocks, thr>>>(rows, cols, vals, sum);
    accum_final_kernel<<<vec_blocks, thr>>>(out);
}

// round 3
// speedup vs baseline: 2.3300x; 2.3300x over previous
#include <cuda_runtime.h>
#include <cuda_fp16.h>

#define N_USERS 100000
#define N_ITEMS 200000
#define N_NODES (N_USERS + N_ITEMS)
#define NNZ     9600000
#define DIM     64
#define TOTAL   ((size_t)N_NODES * DIM)
#define TOTAL4  (TOTAL / 4)

// Double-buffered fp16 layer embeddings (alloc-free rule: __device__ globals).
// Each 38.4MB; both together (76.8MB) stay L2-resident during spmm.
// One buffer is the gather source, the other is the RED-scatter target.
__device__ __align__(16) __half g_h0[TOTAL];
__device__ __align__(16) __half g_h1[TOTAL];

// ---------------------------------------------------------------------------
// init: out(acc) = concat(user,item) fp32; g_h0 = fp16(same); g_h1 = 0.
// Re-done every call so graph replay is deterministic.
// ---------------------------------------------------------------------------
__global__ __launch_bounds__(256) void init_kernel(
    const float* __restrict__ user_emb,
    const float* __restrict__ item_emb,
    float* __restrict__ out)
{
    size_t i = (size_t)blockIdx.x * blockDim.x + threadIdx.x;
    if (i >= TOTAL4) return;
    const size_t ub = (size_t)N_USERS * DIM / 4;
    float4 v = (i < ub) ? ((const float4*)user_emb)[i]
                        : ((const float4*)item_emb)[i - ub];
    ((float4*)out)[i] = v;
    uint2 h;
    __half2 h01 = __floats2half2_rn(v.x, v.y);
    __half2 h23 = __floats2half2_rn(v.z, v.w);
    h.x = *(unsigned*)&h01;
    h.y = *(unsigned*)&h23;
    ((uint2*)g_h0)[i] = h;
    ((uint2*)g_h1)[i] = make_uint2(0u, 0u);
}

// ---------------------------------------------------------------------------
// SpMM scatter: 4 threads per edge. Each thread gathers 8 halfs (16B) from
// src, scales in fp32, repacks, and fires ONE red.global.add.noftz.v4.f16x2
// (16B, adds 8 halfs) into dst. dst must be pre-zeroed.
// 8 L1tex wavefronts per edge total (was 24).
// ---------------------------------------------------------------------------
__global__ __launch_bounds__(256) void spmm_kernel(
    const int*    __restrict__ rows,
    const int*    __restrict__ cols,
    const float*  __restrict__ vals,
    const __half* __restrict__ src,
    __half*       __restrict__ dst)
{
    long long t = (long long)blockIdx.x * blockDim.x + threadIdx.x;
    long long e = t >> 2;
    if (e >= NNZ) return;
    int sub = (int)(t & 3);                 // 4 subs x 16 halfs... no: 4 x 8 halfs... 

    // 4 subs x 16 dims? DIM=64, 4 threads -> 16 dims/thread = 32B. Too big for
    // one uint4. Use 8 dims per thread x ... -> need 8 threads. Correction:
    // 4 threads x 16 halfs requires 2 loads. Instead: sub covers 16 halfs via
    // two uint4 ops? Keep it simple: sub*16 bytes = 8 halfs, and edge needs
    // DIM*2 = 128 bytes -> 8 chunks. With 4 threads, each does 2 chunks.
    const char* sp = (const char*)(src + (size_t)__ldcs(cols + e) * DIM) + (size_t)sub * 16;
    char*       dp = (char*)      (dst + (size_t)__ldcs(rows + e) * DIM) + (size_t)sub * 16;
    float v = __ldcs(vals + e);

    #pragma unroll
    for (int half_blk = 0; half_blk < 2; half_blk++) {
        uint4 raw = __ldg((const uint4*)(sp + half_blk * 64));
        float2 f0 = __half22float2(*(const __half2*)&raw.x);
        float2 f1 = __half22float2(*(const __half2*)&raw.y);
        float2 f2 = __half22float2(*(const __half2*)&raw.z);
        float2 f3 = __half22float2(*(const __half2*)&raw.w);
        __half2 p0 = __floats2half2_rn(f0.x * v, f0.y * v);
        __half2 p1 = __floats2half2_rn(f1.x * v, f1.y * v);
        __half2 p2 = __floats2half2_rn(f2.x * v, f2.y * v);
        __half2 p3 = __floats2half2_rn(f3.x * v, f3.y * v);
        asm volatile("red.global.add.noftz.v4.f16x2 [%0], {%1,%2,%3,%4};"
                     :: "l"(dp + half_blk * 64),
                        "r"(*(unsigned*)&p0), "r"(*(unsigned*)&p1),
                        "r"(*(unsigned*)&p2), "r"(*(unsigned*)&p3)
                     : "memory");
    }
}

// ---------------------------------------------------------------------------
// acc += float(hsum); zero the OTHER fp16 buffer (next layer's RED target).
// ---------------------------------------------------------------------------
__global__ __launch_bounds__(256) void accum_kernel(
    const __half* __restrict__ hsum,
    float*        __restrict__ acc,
    __half*       __restrict__ zbuf)
{
    size_t i = (size_t)blockIdx.x * blockDim.x + threadIdx.x;
    if (i >= TOTAL4) return;
    uint2 h = ((const uint2*)hsum)[i];
    float2 s01 = __half22float2(*(const __half2*)&h.x);
    float2 s23 = __half22float2(*(const __half2*)&h.y);
    float4 a = ((float4*)acc)[i];
    a.x += s01.x; a.y += s01.y; a.z += s23.x; a.w += s23.y;
    ((float4*)acc)[i] = a;
    ((uint2*)zbuf)[i] = make_uint2(0u, 0u);
}

// Final: out = (acc + float(hsum)) * 0.25
__global__ __launch_bounds__(256) void accum_final_kernel(
    const __half* __restrict__ hsum,
    float*        __restrict__ acc)
{
    size_t i = (size_t)blockIdx.x * blockDim.x + threadIdx.x;
    if (i >= TOTAL4) return;
    uint2 h = ((const uint2*)hsum)[i];
    float2 s01 = __half22float2(*(const __half2*)&h.x);
    float2 s23 = __half22float2(*(const __half2*)&h.y);
    float4 a = ((float4*)acc)[i];
    a.x = (a.x + s01.x) * 0.25f;
    a.y = (a.y + s01.y) * 0.25f;
    a.z = (a.z + s23.x) * 0.25f;
    a.w = (a.w + s23.y) * 0.25f;
    ((float4*)acc)[i] = a;
}

extern "C" void kernel_launch(void* const* d_in, const int* in_sizes, int n_in,
                              void* d_out, int out_size)
{
    const int*   rows     = (const int*)  d_in[0];
    const int*   cols     = (const int*)  d_in[1];
    const float* vals     = (const float*)d_in[2];
    const float* user_emb = (const float*)d_in[3];
    const float* item_emb = (const float*)d_in[4];
    float*       out      = (float*)d_out;

    __half *h0, *h1;
    cudaGetSymbolAddress((void**)&h0, g_h0);
    cudaGetSymbolAddress((void**)&h1, g_h1);

    const int thr = 256;
    const long long spmm_threads = (long long)NNZ * 4;
    const int spmm_blocks = (int)((spmm_threads + thr - 1) / thr);
    const int vec_blocks  = (int)((TOTAL4 + thr - 1) / thr);

    // acc = input ; h0 = fp16(input) ; h1 = 0
    init_kernel<<<vec_blocks, thr>>>(user_emb, item_emb, out);

    // Layer 0: gather h0 -> RED into h1 ; acc += h1 ; zero h0
    spmm_kernel<<<spmm_blocks, thr>>>(rows, cols, vals, h0, h1);
    accum_kernel<<<vec_blocks, thr>>>(h1, out, h0);

    // Layer 1: gather h1 -> RED into h0 ; acc += h0 ; zero h1
    spmm_kernel<<<spmm_blocks, thr>>>(rows, cols, vals, h1, h0);
    accum_kernel<<<vec_blocks, thr>>>(h0, out, h1);

    // Layer 2: gather h0 -> RED into h1 ; out = (acc + h1) / 4
    spmm_kernel<<<spmm_blocks, thr>>>(rows, cols, vals, h0, h1);
    accum_final_kernel<<<vec_blocks, thr>>>(h1, out);
}